// round 14
// baseline (speedup 1.0000x reference)
#include <cuda_runtime.h>
#include <cuda_fp16.h>
#include <stdint.h>

#define NN 100000
#define NE 3200000

// ---------------- scratch (static device globals; no allocation) ----------------
// rec layout per node: 32 halves (64B, 64B-aligned):
//   chunk0 (32B): [a+be1 (8h) | q (8h)]  -> col side, one 256-bit load
//   chunk1 (32B): [b (8h)     | p (8h)]  -> row side, one 256-bit load
__device__ __align__(128) __half g_rec[NN * 32];
__device__ __align__(16) float   g_h[NN * 12];    // [H(8), x(3), pad] fp32
__device__ __align__(16) __half  g_s[NN * 8];     // fp16 accum: all messages into v
__device__ __align__(16) int2    g_idx2[NE];      // packed (row, col) int32 (built by edge1)
__device__ int   g_is64;

__constant__ float c_We2[8];
__constant__ float c_be2[1];

// ---------------- math helpers ----------------
__device__ __forceinline__ float ftanh(float x) {
    x = fminf(fmaxf(x, -15.f), 15.f);
    float t = __expf(2.f * x);
    return __fdividef(t - 1.f, t + 1.f);
}
__device__ __forceinline__ float fsig(float x) {
    x = fminf(fmaxf(x, -30.f), 30.f);
    return __fdividef(1.f, 1.f + __expf(-x));
}

// 256-bit scattered load (sm_100a); fills 8 x b32 regs
__device__ __forceinline__ void ldg256(const void* p, unsigned* r) {
    asm volatile("ld.global.nc.v8.f32 {%0,%1,%2,%3,%4,%5,%6,%7}, [%8];"
                 : "=r"(r[0]), "=r"(r[1]), "=r"(r[2]), "=r"(r[3]),
                   "=r"(r[4]), "=r"(r[5]), "=r"(r[6]), "=r"(r[7])
                 : "l"(p));
}
// 128-bit packed-half reduction: 8 halves in ONE instruction
__device__ __forceinline__ void red_add_v4_f16x2(__half* p, __half2 v0, __half2 v1,
                                                 __half2 v2, __half2 v3) {
    asm volatile("red.global.add.noftz.v4.f16x2 [%0], {%1,%2,%3,%4};"
                 :: "l"(p),
                    "r"(*(unsigned*)&v0), "r"(*(unsigned*)&v1),
                    "r"(*(unsigned*)&v2), "r"(*(unsigned*)&v3) : "memory");
}

// ---------------- index dtype detect ----------------
__global__ void k_detect(const unsigned* raw) {
    int ok = 1;
#pragma unroll
    for (int i = 0; i < 32; i++)
        if (raw[2 * i + 1] != 0u) ok = 0;   // int64 LE: high words all zero
    g_is64 = ok;
}

// ---------------- shared edge-pass body (R11 form: 1 edge/thread) ----------------
__device__ __forceinline__ void edge_body(int row, int col) {
    unsigned cU[8], rU[8];
    ldg256(g_rec + col * 32, cU);        // a | q
    ldg256(g_rec + row * 32 + 16, rU);   // b | p

    const __half2* ah = (const __half2*)cU;
    const __half2* qh = (const __half2*)(cU + 4);
    const __half2* bh = (const __half2*)rU;
    const __half2* ph = (const __half2*)(rU + 4);

    float z = c_be2[0];
#pragma unroll
    for (int k = 0; k < 4; k++) {
        float2 t = __half22float2(__hadd2(ah[k], bh[k]));
        z = fmaf(c_We2[2 * k],     ftanh(t.x), z);
        z = fmaf(c_We2[2 * k + 1], ftanh(t.y), z);
    }
    float e = fsig(z);
    __half2 e2 = __float2half2_rn(e);

    red_add_v4_f16x2(g_s + col * 8,
                     __hmul2(e2, ph[0]), __hmul2(e2, ph[1]),
                     __hmul2(e2, ph[2]), __hmul2(e2, ph[3]));
    red_add_v4_f16x2(g_s + row * 8,
                     __hmul2(e2, qh[0]), __hmul2(e2, qh[1]),
                     __hmul2(e2, qh[2]), __hmul2(e2, qh[3]));
}

// first edge pass: also converts raw indices -> packed int2 for later passes
__global__ void k_edge_first(const void* __restrict__ raw)
{
    int j = blockIdx.x * blockDim.x + threadIdx.x;
    if (j >= NE) return;
    int row, col;
    if (g_is64) {
        row = (int)((const long long*)raw)[j];
        col = (int)((const long long*)raw)[NE + j];
    } else {
        row = ((const int*)raw)[j];
        col = ((const int*)raw)[NE + j];
    }
    g_idx2[j] = make_int2(row, col);
    edge_body(row, col);
}

// steady-state edge pass
__global__ void k_edge()
{
    int j = blockIdx.x * blockDim.x + threadIdx.x;
    if (j >= NE) return;
    int2 rc = g_idx2[j];
    edge_body(rc.x, rc.y);
}

// ---------------- scalar record builder (used by init only) ----------------
__device__ __forceinline__ void write_rec_and_clear(
    int v, const float* h, const float* sWe1, const float* sbe1, const float* sWn1)
{
    float a[8], b[8], p[8], q[8];
#pragma unroll
    for (int k = 0; k < 8; k++) { a[k] = sbe1[k]; b[k] = 0.f; p[k] = 0.f; q[k] = 0.f; }
#pragma unroll
    for (int i = 0; i < 11; i++) {
        float hv = h[i];
#pragma unroll
        for (int k = 0; k < 8; k++) {
            a[k] = fmaf(hv, sWe1[i * 8 + k],        a[k]);
            b[k] = fmaf(hv, sWe1[(11 + i) * 8 + k], b[k]);
            p[k] = fmaf(hv, sWn1[i * 8 + k],        p[k]);
            q[k] = fmaf(hv, sWn1[(11 + i) * 8 + k], q[k]);
        }
    }
    __half2* r = (__half2*)(g_rec + v * 32);
    r[0]  = __float22half2_rn(make_float2(a[0], a[1]));
    r[1]  = __float22half2_rn(make_float2(a[2], a[3]));
    r[2]  = __float22half2_rn(make_float2(a[4], a[5]));
    r[3]  = __float22half2_rn(make_float2(a[6], a[7]));
    r[4]  = __float22half2_rn(make_float2(q[0], q[1]));
    r[5]  = __float22half2_rn(make_float2(q[2], q[3]));
    r[6]  = __float22half2_rn(make_float2(q[4], q[5]));
    r[7]  = __float22half2_rn(make_float2(q[6], q[7]));
    r[8]  = __float22half2_rn(make_float2(b[0], b[1]));
    r[9]  = __float22half2_rn(make_float2(b[2], b[3]));
    r[10] = __float22half2_rn(make_float2(b[4], b[5]));
    r[11] = __float22half2_rn(make_float2(b[6], b[7]));
    r[12] = __float22half2_rn(make_float2(p[0], p[1]));
    r[13] = __float22half2_rn(make_float2(p[2], p[3]));
    r[14] = __float22half2_rn(make_float2(p[4], p[5]));
    r[15] = __float22half2_rn(make_float2(p[6], p[7]));

    *(float4*)(g_s + v * 8) = make_float4(0.f, 0.f, 0.f, 0.f);  // 8 halves
}

// ---------------- init (thread per node) ----------------
__global__ void k_init(const float* __restrict__ x,
                       const float* __restrict__ W_in, const float* __restrict__ b_in,
                       const float* __restrict__ We1,  const float* __restrict__ be1,
                       const float* __restrict__ Wn1)
{
    __shared__ float sWin[24], sbin[8], sWe1[176], sbe1[8], sWn1[176];
    int tid = threadIdx.x;
    if (tid < 24) sWin[tid] = W_in[tid];
    if (tid < 8)  sbin[tid] = b_in[tid];
    if (tid < 8)  sbe1[tid] = be1[tid];
    for (int i = tid; i < 176; i += blockDim.x) sWe1[i] = We1[i];
    for (int i = tid; i < 176; i += blockDim.x) sWn1[i] = Wn1[i];
    __syncthreads();

    int v = blockIdx.x * blockDim.x + tid;
    if (v >= NN) return;

    float xv0 = x[v * 3 + 0], xv1 = x[v * 3 + 1], xv2 = x[v * 3 + 2];
    float h[11];
#pragma unroll
    for (int k = 0; k < 8; k++) {
        float s = sbin[k];
        s = fmaf(xv0, sWin[0 * 8 + k], s);
        s = fmaf(xv1, sWin[1 * 8 + k], s);
        s = fmaf(xv2, sWin[2 * 8 + k], s);
        h[k] = ftanh(s);
    }
    h[8] = xv0; h[9] = xv1; h[10] = xv2;

    float4* hp = (float4*)(g_h + v * 12);
    hp[0] = make_float4(h[0], h[1], h[2],  h[3]);
    hp[1] = make_float4(h[4], h[5], h[6],  h[7]);
    hp[2] = make_float4(h[8], h[9], h[10], 0.f);

    write_rec_and_clear(v, h, sWe1, sbe1, sWn1);
}

// ---------------- node pass: 8 LANES PER NODE (lane k owns output column k) ----------------
// NN = 100000 = 3125 blocks * 32 nodes/block exactly -> every 8-lane group is full.
__global__ void __launch_bounds__(256) k_node(
    const float* __restrict__ We1, const float* __restrict__ be1,
    const float* __restrict__ Wn1, const float* __restrict__ bn1,
    const float* __restrict__ Wn2, const float* __restrict__ bn2)
{
    __shared__ float sWe1[176], sbe1[8], sWn1[264], sbn1[8], sWn2[64], sbn2[8];
    int tid = threadIdx.x;
    for (int i = tid; i < 176; i += blockDim.x) sWe1[i] = We1[i];
    for (int i = tid; i < 264; i += blockDim.x) sWn1[i] = Wn1[i];
    for (int i = tid; i < 64;  i += blockDim.x) sWn2[i] = Wn2[i];
    if (tid < 8) { sbe1[tid] = be1[tid]; sbn1[tid] = bn1[tid]; sbn2[tid] = bn2[tid]; }
    __syncthreads();

    int v = blockIdx.x * 32 + (tid >> 3);   // node index (always < NN: exact grid)
    int k = tid & 7;                        // output column

    // broadcast loads of node state (all 8 lanes same address -> L1 broadcast)
    const float4* hp = (const float4*)(g_h + v * 12);
    float4 h0 = hp[0], h1 = hp[1], h2 = hp[2];
    float h[11] = {h0.x, h0.y, h0.z, h0.w, h1.x, h1.y, h1.z, h1.w, h2.x, h2.y, h2.z};

    float msg = __half2float(g_s[v * 8 + k]);   // lane-coalesced 2B load

    // layer 1: pre_k = tanh(msg + bn1_k + h . Wn1[22..32][k])
    float s = msg + sbn1[k];
#pragma unroll
    for (int i = 0; i < 11; i++)
        s = fmaf(h[i], sWn1[(22 + i) * 8 + k], s);
    float pre = ftanh(s);

    // layer 2: hn_k = tanh(bn2_k + sum_j pre_j * Wn2[j][k])  (exchange pre in 8-lane group)
    float s2 = sbn2[k];
#pragma unroll
    for (int j = 0; j < 8; j++) {
        float pj = __shfl_sync(0xffffffffu, pre, j, 8);
        s2 = fmaf(pj, sWn2[j * 8 + k], s2);
    }
    float hn = ftanh(s2);

    g_h[v * 12 + k] = hn;   // x part (h[8..10]) never changes; no rewrite

    // rebuild full h_new via exchange, then compute this lane's record column
    float hnew[11];
#pragma unroll
    for (int j = 0; j < 8; j++)
        hnew[j] = __shfl_sync(0xffffffffu, hn, j, 8);
    hnew[8] = h[8]; hnew[9] = h[9]; hnew[10] = h[10];

    float a = sbe1[k], b = 0.f, p = 0.f, q = 0.f;
#pragma unroll
    for (int i = 0; i < 11; i++) {
        float hv = hnew[i];
        a = fmaf(hv, sWe1[i * 8 + k],        a);
        b = fmaf(hv, sWe1[(11 + i) * 8 + k], b);
        p = fmaf(hv, sWn1[i * 8 + k],        p);
        q = fmaf(hv, sWn1[(11 + i) * 8 + k], q);
    }
    __half* r = g_rec + v * 32;          // [a(8) | q(8) | b(8) | p(8)]
    r[k]      = __float2half_rn(a);
    r[8 + k]  = __float2half_rn(q);
    r[16 + k] = __float2half_rn(b);
    r[24 + k] = __float2half_rn(p);
    g_s[v * 8 + k] = __float2half_rn(0.f);   // clear accumulator
}

// ---------------- final edge pass (2 scattered 16B gathers, coalesced write) ----------------
__global__ void k_out(float* __restrict__ out)
{
    int j = blockIdx.x * blockDim.x + threadIdx.x;
    if (j >= NE) return;
    int2 rc = g_idx2[j];
    int row = rc.x, col = rc.y;

    uint4 aU = *(const uint4*)(g_rec + col * 32);       // a
    uint4 bU = *(const uint4*)(g_rec + row * 32 + 16);  // b
    const __half2* ah = (const __half2*)&aU;
    const __half2* bh = (const __half2*)&bU;

    float z = c_be2[0];
#pragma unroll
    for (int k = 0; k < 4; k++) {
        float2 tt = __half22float2(__hadd2(ah[k], bh[k]));
        z = fmaf(c_We2[2 * k],     ftanh(tt.x), z);
        z = fmaf(c_We2[2 * k + 1], ftanh(tt.y), z);
    }
    out[j] = fsig(z);
}

// ---------------- launch ----------------
extern "C" void kernel_launch(void* const* d_in, const int* in_sizes, int n_in,
                              void* d_out, int out_size)
{
    const float* x    = (const float*)d_in[0];
    const void*  eidx = d_in[1];
    const float* W_in = (const float*)d_in[2];
    const float* b_in = (const float*)d_in[3];
    const float* We1  = (const float*)d_in[4];
    const float* be1  = (const float*)d_in[5];
    const float* We2  = (const float*)d_in[6];
    const float* be2  = (const float*)d_in[7];
    const float* Wn1  = (const float*)d_in[8];
    const float* bn1  = (const float*)d_in[9];
    const float* Wn2  = (const float*)d_in[10];
    const float* bn2  = (const float*)d_in[11];
    float* out = (float*)d_out;

    const int TB = 256;
    const int nodeBlocks  = (NN + TB - 1) / TB;
    const int node8Blocks = NN / 32;               // 3125, exact (8 lanes/node)
    const int edgeBlocks  = (NE + TB - 1) / TB;

    cudaMemcpyToSymbolAsync(c_We2, We2, 8 * sizeof(float), 0, cudaMemcpyDeviceToDevice, 0);
    cudaMemcpyToSymbolAsync(c_be2, be2, 1 * sizeof(float), 0, cudaMemcpyDeviceToDevice, 0);

    k_detect<<<1, 1>>>((const unsigned*)eidx);
    k_init<<<nodeBlocks, TB>>>(x, W_in, b_in, We1, be1, Wn1);
    for (int it = 0; it < 3; it++) {
        if (it == 0) k_edge_first<<<edgeBlocks, TB>>>(eidx);   // converts indices inline
        else         k_edge<<<edgeBlocks, TB>>>();
        k_node<<<node8Blocks, TB>>>(We1, be1, Wn1, bn1, Wn2, bn2);
    }
    k_out<<<edgeBlocks, TB>>>(out);
}

// round 17
// speedup vs baseline: 1.0768x; 1.0768x over previous
#include <cuda_runtime.h>
#include <cuda_fp16.h>
#include <stdint.h>

#define NN 100000
#define NE 3200000

// ---------------- scratch (static device globals; no allocation) ----------------
// rec layout per node: 32 halves (64B, 64B-aligned):
//   chunk0 (32B): [a+be1 (8h) | q (8h)]  -> col side, one 256-bit load
//   chunk1 (32B): [b (8h)     | p (8h)]  -> row side, one 256-bit load
__device__ __align__(128) __half g_rec[NN * 32];
__device__ __align__(16) float   g_h[NN * 12];    // [H(8), x(3), pad] fp32
__device__ __align__(16) __half  g_s[NN * 8];     // fp16 accum: all messages into v
__device__ __align__(16) int2    g_idx2[NE];      // packed (row, col) int32 (built by edge1)
__device__ int   g_is64;

__constant__ float c_We2[8];
__constant__ float c_be2[1];

// ---------------- math helpers ----------------
__device__ __forceinline__ float ftanh(float x) {
    x = fminf(fmaxf(x, -15.f), 15.f);
    float t = __expf(2.f * x);
    return __fdividef(t - 1.f, t + 1.f);
}
__device__ __forceinline__ float fsig(float x) {
    x = fminf(fmaxf(x, -30.f), 30.f);
    return __fdividef(1.f, 1.f + __expf(-x));
}
__device__ __forceinline__ unsigned pkh2(float x, float y) {
    __half2 t = __float22half2_rn(make_float2(x, y));
    return *(unsigned*)&t;
}

// 256-bit scattered load (sm_100a); fills 8 x b32 regs
__device__ __forceinline__ void ldg256(const void* p, unsigned* r) {
    asm volatile("ld.global.nc.v8.f32 {%0,%1,%2,%3,%4,%5,%6,%7}, [%8];"
                 : "=r"(r[0]), "=r"(r[1]), "=r"(r[2]), "=r"(r[3]),
                   "=r"(r[4]), "=r"(r[5]), "=r"(r[6]), "=r"(r[7])
                 : "l"(p));
}
// 128-bit packed-half reduction: 8 halves in ONE instruction
__device__ __forceinline__ void red_add_v4_f16x2(__half* p, __half2 v0, __half2 v1,
                                                 __half2 v2, __half2 v3) {
    asm volatile("red.global.add.noftz.v4.f16x2 [%0], {%1,%2,%3,%4};"
                 :: "l"(p),
                    "r"(*(unsigned*)&v0), "r"(*(unsigned*)&v1),
                    "r"(*(unsigned*)&v2), "r"(*(unsigned*)&v3) : "memory");
}

// ---------------- index dtype detect ----------------
__global__ void k_detect(const unsigned* raw) {
    int ok = 1;
#pragma unroll
    for (int i = 0; i < 32; i++)
        if (raw[2 * i + 1] != 0u) ok = 0;   // int64 LE: high words all zero
    g_is64 = ok;
}

// ---------------- shared edge-pass body (1 edge/thread) ----------------
__device__ __forceinline__ void edge_body(int row, int col) {
    unsigned cU[8], rU[8];
    ldg256(g_rec + col * 32, cU);        // a | q
    ldg256(g_rec + row * 32 + 16, rU);   // b | p

    const __half2* ah = (const __half2*)cU;
    const __half2* qh = (const __half2*)(cU + 4);
    const __half2* bh = (const __half2*)rU;
    const __half2* ph = (const __half2*)(rU + 4);

    float z = c_be2[0];
#pragma unroll
    for (int k = 0; k < 4; k++) {
        float2 t = __half22float2(__hadd2(ah[k], bh[k]));
        z = fmaf(c_We2[2 * k],     ftanh(t.x), z);
        z = fmaf(c_We2[2 * k + 1], ftanh(t.y), z);
    }
    float e = fsig(z);
    __half2 e2 = __float2half2_rn(e);

    red_add_v4_f16x2(g_s + col * 8,
                     __hmul2(e2, ph[0]), __hmul2(e2, ph[1]),
                     __hmul2(e2, ph[2]), __hmul2(e2, ph[3]));
    red_add_v4_f16x2(g_s + row * 8,
                     __hmul2(e2, qh[0]), __hmul2(e2, qh[1]),
                     __hmul2(e2, qh[2]), __hmul2(e2, qh[3]));
}

// first edge pass: also converts raw indices -> packed int2 for later passes
__global__ void k_edge_first(const void* __restrict__ raw)
{
    int j = blockIdx.x * blockDim.x + threadIdx.x;
    if (j >= NE) return;
    int row, col;
    if (g_is64) {
        row = (int)((const long long*)raw)[j];
        col = (int)((const long long*)raw)[NE + j];
    } else {
        row = ((const int*)raw)[j];
        col = ((const int*)raw)[NE + j];
    }
    g_idx2[j] = make_int2(row, col);
    edge_body(row, col);
}

// steady-state edge pass
__global__ void k_edge()
{
    int j = blockIdx.x * blockDim.x + threadIdx.x;
    if (j >= NE) return;
    int2 rc = g_idx2[j];
    edge_body(rc.x, rc.y);
}

// ---------------- record builder: explicit 4 x STG.128 (fp32 compute -> fp16) ----------------
__device__ __forceinline__ void write_rec_and_clear(
    int v, const float* h, const float* sWe1, const float* sbe1, const float* sWn1)
{
    float a[8], b[8], p[8], q[8];
#pragma unroll
    for (int k = 0; k < 8; k++) { a[k] = sbe1[k]; b[k] = 0.f; p[k] = 0.f; q[k] = 0.f; }
#pragma unroll
    for (int i = 0; i < 11; i++) {
        float hv = h[i];
#pragma unroll
        for (int k = 0; k < 8; k++) {
            a[k] = fmaf(hv, sWe1[i * 8 + k],        a[k]);
            b[k] = fmaf(hv, sWe1[(11 + i) * 8 + k], b[k]);
            p[k] = fmaf(hv, sWn1[i * 8 + k],        p[k]);
            q[k] = fmaf(hv, sWn1[(11 + i) * 8 + k], q[k]);
        }
    }
    // pack in registers, emit exactly 4 x 16B stores
    uint4 ua = make_uint4(pkh2(a[0], a[1]), pkh2(a[2], a[3]), pkh2(a[4], a[5]), pkh2(a[6], a[7]));
    uint4 uq = make_uint4(pkh2(q[0], q[1]), pkh2(q[2], q[3]), pkh2(q[4], q[5]), pkh2(q[6], q[7]));
    uint4 ub = make_uint4(pkh2(b[0], b[1]), pkh2(b[2], b[3]), pkh2(b[4], b[5]), pkh2(b[6], b[7]));
    uint4 up = make_uint4(pkh2(p[0], p[1]), pkh2(p[2], p[3]), pkh2(p[4], p[5]), pkh2(p[6], p[7]));
    uint4* r = (uint4*)(g_rec + v * 32);
    r[0] = ua;   // a  (halves 0..7)
    r[1] = uq;   // q  (halves 8..15)
    r[2] = ub;   // b  (halves 16..23)
    r[3] = up;   // p  (halves 24..31)

    *(float4*)(g_s + v * 8) = make_float4(0.f, 0.f, 0.f, 0.f);  // 8 halves cleared
}

// ---------------- init ----------------
__global__ void k_init(const float* __restrict__ x,
                       const float* __restrict__ W_in, const float* __restrict__ b_in,
                       const float* __restrict__ We1,  const float* __restrict__ be1,
                       const float* __restrict__ Wn1)
{
    __shared__ float sWin[24], sbin[8], sWe1[176], sbe1[8], sWn1[176];
    int tid = threadIdx.x;
    if (tid < 24) sWin[tid] = W_in[tid];
    if (tid < 8)  sbin[tid] = b_in[tid];
    if (tid < 8)  sbe1[tid] = be1[tid];
    for (int i = tid; i < 176; i += blockDim.x) sWe1[i] = We1[i];
    for (int i = tid; i < 176; i += blockDim.x) sWn1[i] = Wn1[i];
    __syncthreads();

    int v = blockIdx.x * blockDim.x + tid;
    if (v >= NN) return;

    float xv0 = x[v * 3 + 0], xv1 = x[v * 3 + 1], xv2 = x[v * 3 + 2];
    float h[11];
#pragma unroll
    for (int k = 0; k < 8; k++) {
        float s = sbin[k];
        s = fmaf(xv0, sWin[0 * 8 + k], s);
        s = fmaf(xv1, sWin[1 * 8 + k], s);
        s = fmaf(xv2, sWin[2 * 8 + k], s);
        h[k] = ftanh(s);
    }
    h[8] = xv0; h[9] = xv1; h[10] = xv2;

    float4* hp = (float4*)(g_h + v * 12);
    hp[0] = make_float4(h[0], h[1], h[2],  h[3]);
    hp[1] = make_float4(h[4], h[5], h[6],  h[7]);
    hp[2] = make_float4(h[8], h[9], h[10], 0.f);

    write_rec_and_clear(v, h, sWe1, sbe1, sWn1);
}

// ---------------- node pass (scalar, thread per node; x part of g_h not rewritten) ----------------
__global__ void k_node(const float* __restrict__ We1, const float* __restrict__ be1,
                       const float* __restrict__ Wn1, const float* __restrict__ bn1,
                       const float* __restrict__ Wn2, const float* __restrict__ bn2)
{
    __shared__ float sWe1[176], sbe1[8], sWn1[264], sbn1[8], sWn2[64], sbn2[8];
    int tid = threadIdx.x;
    for (int i = tid; i < 176; i += blockDim.x) sWe1[i] = We1[i];
    for (int i = tid; i < 264; i += blockDim.x) sWn1[i] = Wn1[i];
    for (int i = tid; i < 64;  i += blockDim.x) sWn2[i] = Wn2[i];
    if (tid < 8) { sbe1[tid] = be1[tid]; sbn1[tid] = bn1[tid]; sbn2[tid] = bn2[tid]; }
    __syncthreads();

    int v = blockIdx.x * blockDim.x + tid;
    if (v >= NN) return;

    const float4* hp = (const float4*)(g_h + v * 12);
    float4 h0 = hp[0], h1 = hp[1], h2 = hp[2];
    float h[11] = {h0.x, h0.y, h0.z, h0.w, h1.x, h1.y, h1.z, h1.w, h2.x, h2.y, h2.z};

    uint4 su = *(const uint4*)(g_s + v * 8);   // 8 halves: combined message sum
    const __half2* a1 = (const __half2*)&su;

    float pre[8];
#pragma unroll
    for (int k = 0; k < 4; k++) {
        float2 u = __half22float2(a1[k]);
        pre[2 * k]     = u.x;
        pre[2 * k + 1] = u.y;
    }

#pragma unroll
    for (int k = 0; k < 8; k++) {
        float s = pre[k] + sbn1[k];
#pragma unroll
        for (int i = 0; i < 11; i++)
            s = fmaf(h[i], sWn1[(22 + i) * 8 + k], s);   // M = [mi, mo, h]
        pre[k] = ftanh(s);
    }
    float hn[11];
#pragma unroll
    for (int k = 0; k < 8; k++) {
        float s = sbn2[k];
#pragma unroll
        for (int jj = 0; jj < 8; jj++)
            s = fmaf(pre[jj], sWn2[jj * 8 + k], s);
        hn[k] = ftanh(s);
    }
    hn[8] = h[8]; hn[9] = h[9]; hn[10] = h[10];

    // x part (g_h[v*12+8..11]) is static -> only rewrite H
    float4* hw = (float4*)(g_h + v * 12);
    hw[0] = make_float4(hn[0], hn[1], hn[2],  hn[3]);
    hw[1] = make_float4(hn[4], hn[5], hn[6],  hn[7]);

    write_rec_and_clear(v, hn, sWe1, sbe1, sWn1);
}

// ---------------- final edge pass (2 scattered 16B gathers, coalesced write) ----------------
__global__ void k_out(float* __restrict__ out)
{
    int j = blockIdx.x * blockDim.x + threadIdx.x;
    if (j >= NE) return;
    int2 rc = g_idx2[j];
    int row = rc.x, col = rc.y;

    uint4 aU = *(const uint4*)(g_rec + col * 32);       // a
    uint4 bU = *(const uint4*)(g_rec + row * 32 + 16);  // b
    const __half2* ah = (const __half2*)&aU;
    const __half2* bh = (const __half2*)&bU;

    float z = c_be2[0];
#pragma unroll
    for (int k = 0; k < 4; k++) {
        float2 tt = __half22float2(__hadd2(ah[k], bh[k]));
        z = fmaf(c_We2[2 * k],     ftanh(tt.x), z);
        z = fmaf(c_We2[2 * k + 1], ftanh(tt.y), z);
    }
    out[j] = fsig(z);
}

// ---------------- launch ----------------
extern "C" void kernel_launch(void* const* d_in, const int* in_sizes, int n_in,
                              void* d_out, int out_size)
{
    const float* x    = (const float*)d_in[0];
    const void*  eidx = d_in[1];
    const float* W_in = (const float*)d_in[2];
    const float* b_in = (const float*)d_in[3];
    const float* We1  = (const float*)d_in[4];
    const float* be1  = (const float*)d_in[5];
    const float* We2  = (const float*)d_in[6];
    const float* be2  = (const float*)d_in[7];
    const float* Wn1  = (const float*)d_in[8];
    const float* bn1  = (const float*)d_in[9];
    const float* Wn2  = (const float*)d_in[10];
    const float* bn2  = (const float*)d_in[11];
    float* out = (float*)d_out;

    const int TB = 256;
    const int nodeBlocks = (NN + TB - 1) / TB;
    const int edgeBlocks = (NE + TB - 1) / TB;

    cudaMemcpyToSymbolAsync(c_We2, We2, 8 * sizeof(float), 0, cudaMemcpyDeviceToDevice, 0);
    cudaMemcpyToSymbolAsync(c_be2, be2, 1 * sizeof(float), 0, cudaMemcpyDeviceToDevice, 0);

    k_detect<<<1, 1>>>((const unsigned*)eidx);
    k_init<<<nodeBlocks, TB>>>(x, W_in, b_in, We1, be1, Wn1);
    for (int it = 0; it < 3; it++) {
        if (it == 0) k_edge_first<<<edgeBlocks, TB>>>(eidx);   // converts indices inline
        else         k_edge<<<edgeBlocks, TB>>>();
        k_node<<<nodeBlocks, TB>>>(We1, be1, Wn1, bn1, Wn2, bn2);
    }
    k_out<<<edgeBlocks, TB>>>(out);
}